// round 13
// baseline (speedup 1.0000x reference)
#include <cuda_runtime.h>
#include <math.h>

#define Hn   512
#define Bn   1024
#define Vn   1024
#define Tn   64
#define GENn 100
#define GPAD 104            // GEN padded for unroll (rows 100..103 zero)
#define W1ROWS (Hn + 8)     // 520: 8 pad rows so z-phase ring prefetch never OOB
#define W2ROWS 112          // GEN padded + prefetch slack (rows 100..111 zero)

// ---------------- persistent device scratch (no allocs allowed) ----------------
__device__ float d_Wt[Hn * 4 * Hn];         // [512][2048]  W_hh permuted+transposed
__device__ float d_W1t[W1ROWS * 128];       // [520][128]   W1^T padded
__device__ float d_W2t[W2ROWS * Vn];        // [112][1024]  W2^T padded
__device__ float d_h[2][Bn * Hn];           // ping-pong hidden state
__device__ float d_c[Bn * Hn];              // cell state
__device__ int   d_tok[Bn];                 // current token per batch row

// ---------------- weight re-layout ----------------
__global__ void prep_kernel(const float* __restrict__ W_hh,
                            const float* __restrict__ W1,
                            const float* __restrict__ W2) {
    int id = blockIdx.x * blockDim.x + threadIdx.x;
    const int n1 = Hn * 4 * Hn;             // 1048576
    const int n2 = W1ROWS * 128;            // 66560
    const int n3 = W2ROWS * Vn;             // 114688
    if (id < n1) {
        int k = id >> 11, p = id & 2047;
        int j = p >> 2, g = p & 3;
        d_Wt[id] = W_hh[(g * Hn + j) * Hn + k];
    } else if (id < n1 + n2) {
        int i = id - n1;
        int k = i >> 7, j = i & 127;
        d_W1t[i] = (j < GENn && k < Hn) ? W1[j * Hn + k] : 0.0f;
    } else if (id < n1 + n2 + n3) {
        int i = id - n1 - n2;
        int k = i >> 10, v = i & 1023;
        d_W2t[i] = (k < GENn) ? W2[v * GENn + k] : 0.0f;
    }
}

// ---------------- h0/c0 expansion + initial token ----------------
__global__ void init_kernel(const float* __restrict__ input,
                            const float* __restrict__ Wh, const float* __restrict__ bh,
                            const float* __restrict__ Wc, const float* __restrict__ bc,
                            const float* __restrict__ onehots) {
    int id = blockIdx.x * blockDim.x + threadIdx.x;
    if (id < Bn * Hn) {
        int b = id / Hn, j = id % Hn;
        float x = input[b];
        d_h[0][id] = x * Wh[j] + bh[j];
        d_c[id]    = x * Wc[j] + bc[j];
    } else {
        int i2 = id - Bn * Hn;
        if (i2 < Bn * Vn) {
            int b = i2 >> 10, v = i2 & 1023;
            if (onehots[(size_t)b * (Tn * Vn) + v] > 0.5f) d_tok[b] = v;
        }
    }
}

// ---------------- gates GEMM + fused LSTM cell (at FFMA issue ceiling; unchanged) ----------------
__global__ __launch_bounds__(256) void gates_kernel(
    int cur,
    const float* __restrict__ W_ih,
    const float* __restrict__ b_ih,
    const float* __restrict__ b_hh) {
    __shared__ float As[16][128];
    __shared__ float Bs[16][128];

    const float* hin  = d_h[cur];
    float*       hout = d_h[cur ^ 1];

    int tid = threadIdx.x;
    int tx = tid & 15, ty = tid >> 4;
    int bn0 = blockIdx.x * 128;
    int bm0 = blockIdx.y * 128;

    float acc[8][8];
#pragma unroll
    for (int r = 0; r < 8; r++)
#pragma unroll
        for (int q = 0; q < 8; q++) acc[r][q] = 0.0f;

    for (int k0 = 0; k0 < Hn; k0 += 16) {
#pragma unroll
        for (int i = 0; i < 2; i++) {
            int idx = tid + i * 256;
            int row = idx >> 2;
            int c4  = (idx & 3) * 4;
            float4 v = *(const float4*)&hin[(size_t)(bm0 + row) * Hn + k0 + c4];
            As[c4 + 0][row] = v.x; As[c4 + 1][row] = v.y;
            As[c4 + 2][row] = v.z; As[c4 + 3][row] = v.w;
        }
#pragma unroll
        for (int i = 0; i < 2; i++) {
            int idx = tid + i * 256;
            int row = idx >> 5;
            int c4  = (idx & 31) * 4;
            *(float4*)&Bs[row][c4] = *(const float4*)&d_Wt[(size_t)(k0 + row) * 2048 + bn0 + c4];
        }
        __syncthreads();
#pragma unroll
        for (int kk = 0; kk < 16; kk++) {
            float a[8], bb[8];
            *(float4*)&a[0]  = *(const float4*)&As[kk][ty * 8];
            *(float4*)&a[4]  = *(const float4*)&As[kk][ty * 8 + 4];
            *(float4*)&bb[0] = *(const float4*)&Bs[kk][tx * 8];
            *(float4*)&bb[4] = *(const float4*)&Bs[kk][tx * 8 + 4];
#pragma unroll
            for (int r = 0; r < 8; r++)
#pragma unroll
                for (int q = 0; q < 8; q++) acc[r][q] += a[r] * bb[q];
        }
        __syncthreads();
    }

    int p0 = bn0 + tx * 8;
    int j0 = p0 >> 2;
    float bias[2][4];
#pragma unroll
    for (int jj = 0; jj < 2; jj++)
#pragma unroll
        for (int g = 0; g < 4; g++) {
            int row = g * Hn + (j0 + jj);
            bias[jj][g] = b_ih[row] + b_hh[row];
        }

#pragma unroll
    for (int r = 0; r < 8; r++) {
        int b_idx = bm0 + ty * 8 + r;
        int tk = d_tok[b_idx];
#pragma unroll
        for (int jj = 0; jj < 2; jj++) {
            int j = j0 + jj;
            float gi = acc[r][jj * 4 + 0] + W_ih[(size_t)(0 * Hn + j) * Vn + tk] + bias[jj][0];
            float gf = acc[r][jj * 4 + 1] + W_ih[(size_t)(1 * Hn + j) * Vn + tk] + bias[jj][1];
            float gg = acc[r][jj * 4 + 2] + W_ih[(size_t)(2 * Hn + j) * Vn + tk] + bias[jj][2];
            float go = acc[r][jj * 4 + 3] + W_ih[(size_t)(3 * Hn + j) * Vn + tk] + bias[jj][3];
            float si = 1.0f / (1.0f + expf(-gi));
            float sf = 1.0f / (1.0f + expf(-gf));
            float so = 1.0f / (1.0f + expf(-go));
            float tg = tanhf(gg);
            int   ci = b_idx * Hn + j;
            float cn = sf * d_c[ci] + si * tg;
            d_c[ci]  = cn;
            hout[ci] = so * tanhf(cn);
        }
    }
}

// ---------------- head v4: 1024 threads, 32 warps, halved latency chains ----------------
// z phase:  warp w -> row (w&7), k-quarter (w>>3): 128-iter chain, 8-deep LDG.128 ring.
// logits:   warp w -> 32 vocab cols (lane col), 4-deep scalar LDG ring; zs broadcast LDS.128.
__global__ __launch_bounds__(1024) void head_kernel(
    int nxt,
    const float* __restrict__ b1,
    const float* __restrict__ b2,
    float* __restrict__ out) {
    __shared__ float hs[8][512];        // 16KB
    __shared__ float zpart[32][128];    // 16KB
    __shared__ float zs[GPAD][8];       // k-major z
    __shared__ float red[8][32];
    __shared__ int   redi[8][32];
    __shared__ float gmaxS[8];
    __shared__ float logZS[8];

    const float* __restrict__ h = d_h[nxt];
    int tid = threadIdx.x;
    int w = tid >> 5, l = tid & 31;
    int b0 = blockIdx.x * 8;

    // load 8 h rows (1024 float4, 1 per thread)
    {
        const float4* src = (const float4*)(h + (size_t)b0 * Hn);
        ((float4*)hs)[tid] = src[tid];
    }
    __syncthreads();

    // ---- z partials: row r, k-quarter kq; 128 iters, 8-deep ring ----
    {
        int r  = w & 7;
        int kq = w >> 3;                 // 0..3
        const float4* w1p = (const float4*)d_W1t + (size_t)kq * 128 * 32 + l;
        const float*  hrow = hs[r] + kq * 128;
        float4 ring[8];
#pragma unroll
        for (int i = 0; i < 8; i++) ring[i] = w1p[(size_t)i * 32];
        float4 acc = make_float4(0.f, 0.f, 0.f, 0.f);
#pragma unroll 4
        for (int k = 0; k < 128; k++) {
            float4 cur = ring[k & 7];
            ring[k & 7] = w1p[(size_t)(k + 8) * 32];   // max row 135+384=519 < 520 pad
            float hv = hrow[k];
            acc.x += hv * cur.x; acc.y += hv * cur.y;
            acc.z += hv * cur.z; acc.w += hv * cur.w;
        }
        *(float4*)&zpart[w][4 * l] = acc;
    }
    __syncthreads();

    // combine 4 quarters + bias + relu; transpose to zs[k][r]  (1024 thr = 8r x 128j)
    {
        int r = tid >> 7, j = tid & 127;
        if (j < GPAD) {
            float v = 0.0f;
            if (j < GENn)
                v = fmaxf(zpart[r][j] + zpart[r + 8][j] + zpart[r + 16][j] + zpart[r + 24][j] + b1[j], 0.0f);
            zs[j][r] = v;
        }
    }
    __syncthreads();

    // ---- logits: lane col v = w*32 + l; 8 row-accumulators; 4-deep scalar ring ----
    int v = w * 32 + l;
    float lg[8];
#pragma unroll
    for (int r = 0; r < 8; r++) lg[r] = 0.f;
    {
        const float* w2p = d_W2t + v;            // element k at w2p[k*1024]
        float ring[4];
#pragma unroll
        for (int i = 0; i < 4; i++) ring[i] = w2p[(size_t)i * Vn];
        for (int k0 = 0; k0 < GPAD; k0 += 4) {
#pragma unroll
            for (int i = 0; i < 4; i++) {
                int k = k0 + i;
                float wv = ring[i];
                ring[i] = w2p[(size_t)(k + 4) * Vn];   // max row 107 < 112 pad
                float zv[8];
                *(float4*)&zv[0] = *(const float4*)&zs[k][0];
                *(float4*)&zv[4] = *(const float4*)&zs[k][4];
#pragma unroll
                for (int r = 0; r < 8; r++) lg[r] += wv * zv[r];
            }
        }
        float bb = b2[v];
#pragma unroll
        for (int r = 0; r < 8; r++) lg[r] += bb;
    }

    // ---- per-row max + argmax ----
#pragma unroll
    for (int r = 0; r < 8; r++) {
        float m = lg[r]; int a = v;
#pragma unroll
        for (int o = 16; o > 0; o >>= 1) {
            float m2 = __shfl_xor_sync(0xffffffffu, m, o);
            int   a2 = __shfl_xor_sync(0xffffffffu, a, o);
            if (m2 > m || (m2 == m && a2 < a)) { m = m2; a = a2; }
        }
        if (l == 0) { red[r][w] = m; redi[r][w] = a; }
    }
    __syncthreads();

    if (tid < 8) {   // final max+argmax, first-occurrence tie-break
        float m = red[tid][0]; int a = redi[tid][0];
#pragma unroll
        for (int ww = 1; ww < 32; ww++) {
            float m2 = red[tid][ww]; int a2 = redi[tid][ww];
            if (m2 > m || (m2 == m && a2 < a)) { m = m2; a = a2; }
        }
        d_tok[b0 + tid] = a;
        gmaxS[tid] = m;
    }
    __syncthreads();

    float gmax[8];
#pragma unroll
    for (int r = 0; r < 8; r++) gmax[r] = gmaxS[r];

    // ---- per-row sum(exp(x - max)) ----
#pragma unroll
    for (int r = 0; r < 8; r++) {
        float s = expf(lg[r] - gmax[r]);
#pragma unroll
        for (int o = 16; o > 0; o >>= 1) s += __shfl_xor_sync(0xffffffffu, s, o);
        if (l == 0) red[r][w] = s;
    }
    __syncthreads();

    if (tid < 8) {
        float s = 0.0f;
#pragma unroll
        for (int ww = 0; ww < 32; ww++) s += red[tid][ww];
        logZS[tid] = logf(s);
    }
    __syncthreads();

    float logZ[8];
#pragma unroll
    for (int r = 0; r < 8; r++) logZ[r] = logZS[r];

    // ---- write logp (1 col per lane, 8 rows; coalesced 128B/warp/row) ----
#pragma unroll
    for (int r = 0; r < 8; r++)
        out[(size_t)(b0 + r) * Vn + v] = lg[r] - gmax[r] - logZ[r];
}

// ---------------- launch ----------------
extern "C" void kernel_launch(void* const* d_in, const int* in_sizes, int n_in,
                              void* d_out, int out_size) {
    (void)out_size;
    int off = (n_in >= 16 && in_sizes[3] == 1) ? 4 : 3;
    const float* input   = (const float*)d_in[0];
    const float* onehots = (const float*)d_in[1];
    const float* Wh   = (const float*)d_in[off + 0];
    const float* bh   = (const float*)d_in[off + 1];
    const float* Wc   = (const float*)d_in[off + 2];
    const float* bc   = (const float*)d_in[off + 3];
    const float* W_ih = (const float*)d_in[off + 4];
    const float* W_hh = (const float*)d_in[off + 5];
    const float* b_ih = (const float*)d_in[off + 6];
    const float* b_hh = (const float*)d_in[off + 7];
    const float* W1   = (const float*)d_in[off + 8];
    const float* b1   = (const float*)d_in[off + 9];
    const float* W2   = (const float*)d_in[off + 10];
    const float* b2   = (const float*)d_in[off + 11];
    float* out = (float*)d_out;

    const int prepN = Hn * 4 * Hn + W1ROWS * 128 + W2ROWS * Vn;
    prep_kernel<<<(prepN + 255) / 256, 256>>>(W_hh, W1, W2);

    const int initN = Bn * Hn + Bn * Vn;
    init_kernel<<<(initN + 255) / 256, 256>>>(input, Wh, bh, Wc, bc, onehots);

    for (int t = 0; t < Tn; t++) {
        int cur = t & 1;
        gates_kernel<<<dim3(16, 8), 256>>>(cur, W_ih, b_ih, b_hh);
        head_kernel<<<128, 1024>>>(cur ^ 1, b1, b2, out + (size_t)t * Bn * Vn);
    }
}